// round 13
// baseline (speedup 1.0000x reference)
#include <cuda_runtime.h>

// Problem constants
#define SEQ   2048
#define BATCH 128
#define EDIM  128
#define LDIM  128
#define GDIM  512   // 4*L
#define NCLS  2

typedef unsigned long long ull;

// ---- packed fp32x2 helpers (Blackwell f32x2 datapath, PTX-only) ----
__device__ __forceinline__ ull ffma2(ull a, ull b, ull c) {
    ull d;
    asm("fma.rn.f32x2 %0, %1, %2, %3;" : "=l"(d) : "l"(a), "l"(b), "l"(c));
    return d;
}
__device__ __forceinline__ ull pack2(float lo, float hi) {
    ull r; asm("mov.b64 %0, {%1, %2};" : "=l"(r) : "f"(lo), "f"(hi)); return r;
}
__device__ __forceinline__ float2 unpack2(ull v) {
    float2 f; asm("mov.b64 {%0, %1}, %2;" : "=f"(f.x), "=f"(f.y) : "l"(v));
    return f;
}
__device__ __forceinline__ float hsum2(ull v) {
    float2 p = unpack2(v); return p.x + p.y;
}

// 512 MB scratch for precomputed input projections xg[t][b][g]
__device__ float g_xg[(size_t)SEQ * BATCH * GDIM];

// ============================================================
// Phase 1: xg = x @ Wi + bi    ([262144 x 128] * [128 x 512])
// R2 config (measured ~825us): 256 threads, 4x8 outputs/thread,
// 2 CTAs/SM (16 warps). Columns strided (tx + 16j), stride 130
// floats -> conflict-free b-loads.
// ============================================================
#define TM 64
#define TN 128
#define BS_STRIDE 130

__global__ __launch_bounds__(256, 2)
void xproj_kernel(const float* __restrict__ x, const float* __restrict__ Wi,
                  const float* __restrict__ bi) {
    extern __shared__ float sm[];
    float* As = sm;                 // [64][128]
    float* Bs = sm + TM * EDIM;     // [128 cols][130] transposed Wi slice

    const int tid = threadIdx.x;
    const size_t row0 = (size_t)blockIdx.x * TM;
    const int c0 = blockIdx.y * TN;

    // A tile: 64 contiguous rows of x (32KB)
    {
        const float4* xa = (const float4*)(x + row0 * EDIM);
        float4* As4 = (float4*)As;
        #pragma unroll
        for (int i = 0; i < 8; i++) As4[tid + 256 * i] = xa[tid + 256 * i];
    }
    // B tile: Bs[c][k] = Wi[k][c0+c]  (transpose so K is contiguous)
    {
        const int c  = tid & 127;
        const int kh = tid >> 7;    // 0 or 1
        #pragma unroll 8
        for (int it = 0; it < 64; it++) {
            int k = it * 2 + kh;
            Bs[c * BS_STRIDE + k] = Wi[k * GDIM + c0 + c];
        }
    }
    __syncthreads();

    const int tx = tid & 15;    // columns: tx + 16j, j in [0,8)
    const int ty = tid >> 4;    // row group
    const int rbase = ty * 4;

    ull acc[4][8];
    #pragma unroll
    for (int i = 0; i < 4; i++)
        #pragma unroll
        for (int j = 0; j < 8; j++) acc[i][j] = 0ULL;

    const ull* ap = (const ull*)&As[rbase * EDIM];          // a pairs
    const ull* bp = (const ull*)&Bs[tx * BS_STRIDE];        // b pairs (col tx)
    const int BSU = BS_STRIDE / 2;                          // 65 ull per col

    #pragma unroll 8
    for (int kk = 0; kk < 64; kk++) {       // k-pairs
        ull a2[4], b2[8];
        #pragma unroll
        for (int i = 0; i < 4; i++) a2[i] = ap[i * (EDIM / 2) + kk];
        #pragma unroll
        for (int j = 0; j < 8; j++) b2[j] = bp[j * 16 * BSU + kk];
        #pragma unroll
        for (int i = 0; i < 4; i++)
            #pragma unroll
            for (int j = 0; j < 8; j++)
                acc[i][j] = ffma2(a2[i], b2[j], acc[i][j]);
    }

    float bival[8];
    #pragma unroll
    for (int j = 0; j < 8; j++) bival[j] = bi[c0 + tx + 16 * j];

    #pragma unroll
    for (int i = 0; i < 4; i++) {
        size_t base = (row0 + rbase + i) * (size_t)GDIM + (size_t)(c0 + tx);
        #pragma unroll
        for (int j = 0; j < 8; j++)
            g_xg[base + 16 * j] = hsum2(acc[i][j]) + bival[j];
    }
}

// ============================================================
// Phase 2: persistent LSTM. One CTA per batch, 256 threads.
// Lane-pair gate mapping: q = tid&1, u = tid>>1.
//   colA = q*128 + u     (q0: f,  q1: i)
//   colB = 256 + colA    (q0: g~, q1: o)
// Act exchange via 2x shfl.xor(1) (adjacent lanes) - no smem xch.
// h double-buffered -> ONE __syncthreads per step.
// Weights: 46 k-pairs/col in regs (184), 18 in smem (72KB).
// LDS floor/step: h-broadcast 256 + weights 576 = 832 cyc.
// ============================================================
#define WREG  46                    // reg k-pairs per column (even)
#define WSM   (64 - WREG)           // 18 smem k-pairs per column
#define NJJ   (WREG / 2)            // 23 reg jj iterations
#define SJJ   (WSM / 2)             // 9 smem jj iterations

__global__ __launch_bounds__(256, 1)
void lstm_kernel(const float* __restrict__ Wh, const float* __restrict__ bh,
                 const float* __restrict__ Wc, const float* __restrict__ bc,
                 float* __restrict__ out) {
    extern __shared__ char smraw[];
    float*      hbuf = (float*)smraw;                    // [2][128] h buffers
    ulonglong2* wsA  = (ulonglong2*)(smraw + 1024);      // [SJJ][256]
    ulonglong2* wsB  = wsA + SJJ * 256;                  // [SJJ][256]

    const int tid = threadIdx.x;
    const int b   = blockIdx.x;
    const int q   = tid & 1;         // 0: f,g~   1: i,o
    const int u   = tid >> 1;        // hidden unit
    const int gA  = q * LDIM + u;
    const int gB  = 2 * LDIM + gA;

    // Register weights: pair p of col = (Wh[2p][g], Wh[2p+1][g])
    ull wrA[WREG], wrB[WREG];
    #pragma unroll
    for (int p = 0; p < WREG; p++) {
        wrA[p] = pack2(Wh[(2 * p) * GDIM + gA], Wh[(2 * p + 1) * GDIM + gA]);
        wrB[p] = pack2(Wh[(2 * p) * GDIM + gB], Wh[(2 * p + 1) * GDIM + gB]);
    }
    // Smem weights: jj covers k-pairs (2jj, 2jj+1), jj in [NJJ, 32)
    #pragma unroll
    for (int s = 0; s < SJJ; s++) {
        int p0 = WREG + 2 * s, p1 = p0 + 1;
        ulonglong2 va, vb;
        va.x = pack2(Wh[(2 * p0) * GDIM + gA], Wh[(2 * p0 + 1) * GDIM + gA]);
        va.y = pack2(Wh[(2 * p1) * GDIM + gA], Wh[(2 * p1 + 1) * GDIM + gA]);
        vb.x = pack2(Wh[(2 * p0) * GDIM + gB], Wh[(2 * p0 + 1) * GDIM + gB]);
        vb.y = pack2(Wh[(2 * p1) * GDIM + gB], Wh[(2 * p1 + 1) * GDIM + gB]);
        wsA[s * 256 + tid] = va;
        wsB[s * 256 + tid] = vb;
    }
    const float bhA = bh[gA];
    const float bhB = bh[gB];
    if (q == 0) hbuf[u] = 0.0f;       // buffer 0 = h_0 = 0
    float c_state = 0.0f;
    __syncthreads();

    const float* xgA_p = g_xg + (size_t)b * GDIM + gA;
    const float* xgB_p = g_xg + (size_t)b * GDIM + gB;
    const unsigned FULL = 0xFFFFFFFFu;
    const float mB = (q == 0) ? 2.0f : 1.0f;   // tanh = 2*sig(2x)-1 for g~

    const float* hr = hbuf;           // read buffer
    float*       hw = hbuf + LDIM;    // write buffer

    for (int t = 0; t < SEQ; t++) {
        // this step's input projections (LDG hides under the dot)
        float xgA = __ldcs(xgA_p);
        float xgB = __ldcs(xgB_p);
        xgA_p += BATCH * GDIM;
        xgB_p += BATCH * GDIM;

        const ulonglong2* hq = (const ulonglong2*)hr;   // broadcast .128
        ull a0 = 0ULL, a1 = 0ULL, b0 = 0ULL, b1 = 0ULL;
        #pragma unroll
        for (int jj = 0; jj < NJJ; jj++) {              // k-pairs 0..2*NJJ-1
            ulonglong2 hh = hq[jj];
            a0 = ffma2(wrA[2 * jj],     hh.x, a0);
            a1 = ffma2(wrA[2 * jj + 1], hh.y, a1);
            b0 = ffma2(wrB[2 * jj],     hh.x, b0);
            b1 = ffma2(wrB[2 * jj + 1], hh.y, b1);
        }
        #pragma unroll
        for (int s = 0; s < SJJ; s++) {                 // k-pairs WREG..63
            ulonglong2 hh = hq[NJJ + s];
            ulonglong2 wa = wsA[s * 256 + tid];
            ulonglong2 wb = wsB[s * 256 + tid];
            a0 = ffma2(wa.x, hh.x, a0);
            a1 = ffma2(wa.y, hh.y, a1);
            b0 = ffma2(wb.x, hh.x, b0);
            b1 = ffma2(wb.y, hh.y, b1);
        }
        float gateA = hsum2(a0) + hsum2(a1) + xgA + bhA;
        float gateB = hsum2(b0) + hsum2(b1) + xgB + bhB;

        // acts: actA = sig(gateA) [f or i]; actB = tanh/sig(gateB) [g~ or o]
        float actA = __fdividef(1.0f, 1.0f + __expf(-gateA));
        float s2   = __fdividef(1.0f, 1.0f + __expf(-mB * gateB));
        float actB = (q == 0) ? (2.0f * s2 - 1.0f) : s2;

        // exchange with adjacent lane (partner holds the other 2 gates)
        float oA = __shfl_xor_sync(FULL, actA, 1);
        float oB = __shfl_xor_sync(FULL, actB, 1);

        if (q == 0) {                 // owns c[u], h[u]
            c_state = actA * c_state + oA * actB;       // f*c + i*g~
            float sg = __fdividef(1.0f, 1.0f + __expf(-2.0f * c_state));
            hw[u] = oB * (2.0f * sg - 1.0f);            // o * tanh(c)
        }
        __syncthreads();
        const float* tmp = hr; hr = hw; hw = (float*)tmp;
    }

    // Final classifier (last barrier already taken inside the loop)
    if (tid < NCLS) {
        float sum = bc[tid];
        #pragma unroll 8
        for (int l = 0; l < LDIM; l++) sum += hr[l] * Wc[l * NCLS + tid];
        out[b * NCLS + tid] = sum;
    }
}

// ============================================================
// Launch
// ============================================================
extern "C" void kernel_launch(void* const* d_in, const int* in_sizes, int n_in,
                              void* d_out, int out_size) {
    const float* x  = (const float*)d_in[0];
    const float* Wi = (const float*)d_in[1];
    const float* bi = (const float*)d_in[2];
    const float* Wh = (const float*)d_in[3];
    const float* bh = (const float*)d_in[4];
    const float* Wc = (const float*)d_in[5];
    const float* bc = (const float*)d_in[6];
    float* out = (float*)d_out;

    const int smem1 = (TM * EDIM + TN * BS_STRIDE) * 4;      // 99,328 B
    const int smem2 = 1024 + 2 * SJJ * 256 * 16;             // 74,752 B
    cudaFuncSetAttribute(xproj_kernel,
                         cudaFuncAttributeMaxDynamicSharedMemorySize, smem1);
    cudaFuncSetAttribute(lstm_kernel,
                         cudaFuncAttributeMaxDynamicSharedMemorySize, smem2);

    dim3 grid1((SEQ * BATCH) / TM, GDIM / TN);   // 4096 x 4
    xproj_kernel<<<grid1, 256, smem1>>>(x, Wi, bi);
    lstm_kernel<<<BATCH, 256, smem2>>>(Wh, bh, Wc, bc, out);
}

// round 14
// speedup vs baseline: 1.2542x; 1.2542x over previous
#include <cuda_runtime.h>

// Problem constants
#define SEQ   2048
#define BATCH 128
#define EDIM  128
#define LDIM  128
#define GDIM  512   // 4*L
#define NCLS  2

typedef unsigned long long ull;

// ---- packed fp32x2 helpers (Blackwell f32x2 datapath, PTX-only) ----
__device__ __forceinline__ ull ffma2(ull a, ull b, ull c) {
    ull d;
    asm("fma.rn.f32x2 %0, %1, %2, %3;" : "=l"(d) : "l"(a), "l"(b), "l"(c));
    return d;
}
__device__ __forceinline__ ull pack2(float lo, float hi) {
    ull r; asm("mov.b64 %0, {%1, %2};" : "=l"(r) : "f"(lo), "f"(hi)); return r;
}
__device__ __forceinline__ float2 unpack2(ull v) {
    float2 f; asm("mov.b64 {%0, %1}, %2;" : "=f"(f.x), "=f"(f.y) : "l"(v));
    return f;
}
__device__ __forceinline__ float hsum2(ull v) {
    float2 p = unpack2(v); return p.x + p.y;
}

// 512 MB scratch for precomputed input projections xg[t][b][g]
__device__ float g_xg[(size_t)SEQ * BATCH * GDIM];

// ============================================================
// Phase 1: xg = x @ Wi + bi    ([262144 x 128] * [128 x 512])
// R2 config (measured ~820us): 256 threads, 4x8 outputs/thread,
// 2 CTAs/SM. Columns strided (tx + 16j), stride 130 floats ->
// conflict-free b-loads.
// ============================================================
#define TM 64
#define TN 128
#define BS_STRIDE 130

__global__ __launch_bounds__(256, 2)
void xproj_kernel(const float* __restrict__ x, const float* __restrict__ Wi,
                  const float* __restrict__ bi) {
    extern __shared__ float sm[];
    float* As = sm;                 // [64][128]
    float* Bs = sm + TM * EDIM;     // [128 cols][130] transposed Wi slice

    const int tid = threadIdx.x;
    const size_t row0 = (size_t)blockIdx.x * TM;
    const int c0 = blockIdx.y * TN;

    // A tile: 64 contiguous rows of x (32KB)
    {
        const float4* xa = (const float4*)(x + row0 * EDIM);
        float4* As4 = (float4*)As;
        #pragma unroll
        for (int i = 0; i < 8; i++) As4[tid + 256 * i] = xa[tid + 256 * i];
    }
    // B tile: Bs[c][k] = Wi[k][c0+c]  (transpose so K is contiguous)
    {
        const int c  = tid & 127;
        const int kh = tid >> 7;    // 0 or 1
        #pragma unroll 8
        for (int it = 0; it < 64; it++) {
            int k = it * 2 + kh;
            Bs[c * BS_STRIDE + k] = Wi[k * GDIM + c0 + c];
        }
    }
    __syncthreads();

    const int tx = tid & 15;    // columns: tx + 16j, j in [0,8)
    const int ty = tid >> 4;    // row group
    const int rbase = ty * 4;

    ull acc[4][8];
    #pragma unroll
    for (int i = 0; i < 4; i++)
        #pragma unroll
        for (int j = 0; j < 8; j++) acc[i][j] = 0ULL;

    const ull* ap = (const ull*)&As[rbase * EDIM];          // a pairs
    const ull* bp = (const ull*)&Bs[tx * BS_STRIDE];        // b pairs (col tx)
    const int BSU = BS_STRIDE / 2;                          // 65 ull per col

    #pragma unroll 8
    for (int kk = 0; kk < 64; kk++) {       // k-pairs
        ull a2[4], b2[8];
        #pragma unroll
        for (int i = 0; i < 4; i++) a2[i] = ap[i * (EDIM / 2) + kk];
        #pragma unroll
        for (int j = 0; j < 8; j++) b2[j] = bp[j * 16 * BSU + kk];
        #pragma unroll
        for (int i = 0; i < 4; i++)
            #pragma unroll
            for (int j = 0; j < 8; j++)
                acc[i][j] = ffma2(a2[i], b2[j], acc[i][j]);
    }

    float bival[8];
    #pragma unroll
    for (int j = 0; j < 8; j++) bival[j] = bi[c0 + tx + 16 * j];

    #pragma unroll
    for (int i = 0; i < 4; i++) {
        size_t base = (row0 + rbase + i) * (size_t)GDIM + (size_t)(c0 + tx);
        #pragma unroll
        for (int j = 0; j < 8; j++)
            g_xg[base + 16 * j] = hsum2(acc[i][j]) + bival[j];
    }
}

// ============================================================
// Phase 2: persistent LSTM. One CTA per batch, 256 threads.
// Lane-pair gate mapping: q = tid&1, u = tid>>1.
//   colA = q*128 + u     (q0: f,  q1: i)
//   colB = 256 + colA    (q0: g~, q1: o)
// Act exchange via 2x shfl.xor(1); h double-buffered -> ONE
// __syncthreads per step. xg prefetched ONE STEP AHEAD so its
// DRAM latency hides under the previous step's dot (the R13
// regression was removing this prefetch).
// Weights: 46 k-pairs/col in regs (184), 18 in smem (72KB).
// ============================================================
#define WREG  46                    // reg k-pairs per column (even)
#define WSM   (64 - WREG)           // 18 smem k-pairs per column
#define NJJ   (WREG / 2)            // 23 reg jj iterations
#define SJJ   (WSM / 2)             // 9 smem jj iterations

__global__ __launch_bounds__(256, 1)
void lstm_kernel(const float* __restrict__ Wh, const float* __restrict__ bh,
                 const float* __restrict__ Wc, const float* __restrict__ bc,
                 float* __restrict__ out) {
    extern __shared__ char smraw[];
    float*      hbuf = (float*)smraw;                    // [2][128] h buffers
    ulonglong2* wsA  = (ulonglong2*)(smraw + 1024);      // [SJJ][256]
    ulonglong2* wsB  = wsA + SJJ * 256;                  // [SJJ][256]

    const int tid = threadIdx.x;
    const int b   = blockIdx.x;
    const int q   = tid & 1;         // 0: f,g~   1: i,o
    const int u   = tid >> 1;        // hidden unit
    const int gA  = q * LDIM + u;
    const int gB  = 2 * LDIM + gA;

    // Register weights: pair p of col = (Wh[2p][g], Wh[2p+1][g])
    ull wrA[WREG], wrB[WREG];
    #pragma unroll
    for (int p = 0; p < WREG; p++) {
        wrA[p] = pack2(Wh[(2 * p) * GDIM + gA], Wh[(2 * p + 1) * GDIM + gA]);
        wrB[p] = pack2(Wh[(2 * p) * GDIM + gB], Wh[(2 * p + 1) * GDIM + gB]);
    }
    // Smem weights: jj covers k-pairs (2jj, 2jj+1), jj in [NJJ, 32)
    #pragma unroll
    for (int s = 0; s < SJJ; s++) {
        int p0 = WREG + 2 * s, p1 = p0 + 1;
        ulonglong2 va, vb;
        va.x = pack2(Wh[(2 * p0) * GDIM + gA], Wh[(2 * p0 + 1) * GDIM + gA]);
        va.y = pack2(Wh[(2 * p1) * GDIM + gA], Wh[(2 * p1 + 1) * GDIM + gA]);
        vb.x = pack2(Wh[(2 * p0) * GDIM + gB], Wh[(2 * p0 + 1) * GDIM + gB]);
        vb.y = pack2(Wh[(2 * p1) * GDIM + gB], Wh[(2 * p1 + 1) * GDIM + gB]);
        wsA[s * 256 + tid] = va;
        wsB[s * 256 + tid] = vb;
    }
    const float bhA = bh[gA];
    const float bhB = bh[gB];
    if (q == 0) hbuf[u] = 0.0f;       // buffer 0 = h_0 = 0
    float c_state = 0.0f;
    __syncthreads();

    const float* xgA_p = g_xg + (size_t)b * GDIM + gA;
    const float* xgB_p = g_xg + (size_t)b * GDIM + gB;
    const unsigned FULL = 0xFFFFFFFFu;
    const float mB = (q == 0) ? 2.0f : 1.0f;   // tanh = 2*sig(2x)-1 for g~

    const float* hr = hbuf;           // read buffer
    float*       hw = hbuf + LDIM;    // write buffer

    float xgA = __ldcs(xgA_p);        // t = 0 projections
    float xgB = __ldcs(xgB_p);

    for (int t = 0; t < SEQ; t++) {
        // prefetch NEXT step's projections; latency hides under this dot
        size_t noff = (size_t)((t + 1) & (SEQ - 1)) * (BATCH * GDIM);
        float xgA_n = __ldcs(xgA_p + noff);
        float xgB_n = __ldcs(xgB_p + noff);

        const ulonglong2* hq = (const ulonglong2*)hr;   // broadcast .128
        ull a0 = 0ULL, a1 = 0ULL, b0 = 0ULL, b1 = 0ULL;
        #pragma unroll
        for (int jj = 0; jj < NJJ; jj++) {              // k-pairs 0..2*NJJ-1
            ulonglong2 hh = hq[jj];
            a0 = ffma2(wrA[2 * jj],     hh.x, a0);
            a1 = ffma2(wrA[2 * jj + 1], hh.y, a1);
            b0 = ffma2(wrB[2 * jj],     hh.x, b0);
            b1 = ffma2(wrB[2 * jj + 1], hh.y, b1);
        }
        #pragma unroll
        for (int s = 0; s < SJJ; s++) {                 // k-pairs WREG..63
            ulonglong2 hh = hq[NJJ + s];
            ulonglong2 wa = wsA[s * 256 + tid];
            ulonglong2 wb = wsB[s * 256 + tid];
            a0 = ffma2(wa.x, hh.x, a0);
            a1 = ffma2(wa.y, hh.y, a1);
            b0 = ffma2(wb.x, hh.x, b0);
            b1 = ffma2(wb.y, hh.y, b1);
        }
        float gateA = hsum2(a0) + hsum2(a1) + xgA + bhA;
        float gateB = hsum2(b0) + hsum2(b1) + xgB + bhB;

        // acts: actA = sig(gateA) [f or i]; actB = tanh/sig(gateB) [g~ or o]
        float actA = __fdividef(1.0f, 1.0f + __expf(-gateA));
        float s2   = __fdividef(1.0f, 1.0f + __expf(-mB * gateB));
        float actB = (q == 0) ? (2.0f * s2 - 1.0f) : s2;

        // exchange with adjacent lane (partner holds the other 2 gates)
        float oA = __shfl_xor_sync(FULL, actA, 1);
        float oB = __shfl_xor_sync(FULL, actB, 1);

        if (q == 0) {                 // owns c[u], h[u]
            c_state = actA * c_state + oA * actB;       // f*c + i*g~
            float sg = __fdividef(1.0f, 1.0f + __expf(-2.0f * c_state));
            hw[u] = oB * (2.0f * sg - 1.0f);            // o * tanh(c)
        }
        xgA = xgA_n; xgB = xgB_n;
        __syncthreads();
        const float* tmp = hr; hr = hw; hw = (float*)tmp;
    }

    // Final classifier
    if (tid < NCLS) {
        float sum = bc[tid];
        #pragma unroll 8
        for (int l = 0; l < LDIM; l++) sum += hr[l] * Wc[l * NCLS + tid];
        out[b * NCLS + tid] = sum;
    }
}

// ============================================================
// Launch
// ============================================================
extern "C" void kernel_launch(void* const* d_in, const int* in_sizes, int n_in,
                              void* d_out, int out_size) {
    const float* x  = (const float*)d_in[0];
    const float* Wi = (const float*)d_in[1];
    const float* bi = (const float*)d_in[2];
    const float* Wh = (const float*)d_in[3];
    const float* bh = (const float*)d_in[4];
    const float* Wc = (const float*)d_in[5];
    const float* bc = (const float*)d_in[6];
    float* out = (float*)d_out;

    const int smem1 = (TM * EDIM + TN * BS_STRIDE) * 4;      // 99,328 B
    const int smem2 = 1024 + 2 * SJJ * 256 * 16;             // 74,752 B
    cudaFuncSetAttribute(xproj_kernel,
                         cudaFuncAttributeMaxDynamicSharedMemorySize, smem1);
    cudaFuncSetAttribute(lstm_kernel,
                         cudaFuncAttributeMaxDynamicSharedMemorySize, smem2);

    dim3 grid1((SEQ * BATCH) / TM, GDIM / TN);   // 4096 x 4
    xproj_kernel<<<grid1, 256, smem1>>>(x, Wi, bi);
    lstm_kernel<<<BATCH, 256, smem2>>>(Wh, bh, Wc, bc, out);
}